// round 1
// baseline (speedup 1.0000x reference)
#include <cuda_runtime.h>
#include <cstdint>

// Problem-shape capacities (actual B,N,C derived at launch; these bound scratch)
#define MAXB 16
#define MAXN 24564
#define MAXC 81
#define CAP  2048      // per-(b,c) candidate shortlist capacity
#define KPC  50        // MAX_PER_CLASS
#define MAXTOT 200
#define THETA 0.98f    // shortlist score threshold ( > SCORE_THR=0.5 )
#define PREF 256       // prefetched candidate boxes per block

// ---------------- static device scratch (no runtime allocation) ----------------
__device__ float4 g_boxes[MAXB * MAXN];                    // decoded boxes
__device__ unsigned char g_mask[MAXB * MAXN];              // argmax!=0 mask
__device__ unsigned long long g_cand[(size_t)MAXB * MAXC * CAP]; // packed (score,~n)
__device__ int g_candCnt[MAXB * MAXC];
__device__ int g_tot05[MAXB * MAXC];                       // # masked scores > 0.5
__device__ float g_keptScore[MAXB * MAXC * KPC];
__device__ int   g_keptN[MAXB * MAXC * KPC];

__device__ __forceinline__ float iouf(float4 a, float4 b) {
    float iy1 = fmaxf(a.x, b.x);
    float ix1 = fmaxf(a.y, b.y);
    float iy2 = fminf(a.z, b.z);
    float ix2 = fminf(a.w, b.w);
    float inter = fmaxf(iy2 - iy1, 0.f) * fmaxf(ix2 - ix1, 0.f);
    float a0 = (a.z - a.x) * (a.w - a.y);
    float a1 = (b.z - b.x) * (b.w - b.y);
    return inter / (a0 + a1 - inter + 1e-8f);
}

__global__ void zero_kernel(int n) {
    int i = blockIdx.x * blockDim.x + threadIdx.x;
    if (i < n) { g_candCnt[i] = 0; g_tot05[i] = 0; }
}

// ---------------- Phase A: fused argmax-mask + decode + candidate collection ----
// One block handles 32 anchors of one batch. Reads pred_labels once, coalesced.
__global__ __launch_bounds__(256) void phaseA(
    const float* __restrict__ labels,   // (B,N,C)
    const float* __restrict__ deltas,   // (B,N,4)
    const float* __restrict__ priors,   // (N,4)
    int B, int N, int C)
{
    int tilesPerB = (N + 31) >> 5;
    int b = blockIdx.x / tilesPerB;
    int tile = blockIdx.x - b * tilesPerB;
    int n0 = tile * 32;
    int na = min(32, N - n0);

    __shared__ float sm[32 * MAXC];
    __shared__ int s_mask[32];
    __shared__ int s_cnt05[MAXC];

    int tid = threadIdx.x;
    int tot = na * C;
    const float* Lbase = labels + ((size_t)b * N + n0) * C;
    for (int i = tid; i < tot; i += 256) sm[i] = Lbase[i];
    for (int i = tid; i < C; i += 256) s_cnt05[i] = 0;
    __syncthreads();

    // per-anchor argmax over C classes (first index on ties, matches jnp.argmax)
    int wid = tid >> 5, lane = tid & 31;
    for (int a = wid; a < na; a += 8) {
        float bv = -1e30f; int bi = 0x7fffffff;
        for (int j = lane; j < C; j += 32) {
            float v = sm[a * C + j];
            if (v > bv) { bv = v; bi = j; }
        }
        for (int off = 16; off; off >>= 1) {
            float ov = __shfl_xor_sync(0xffffffffu, bv, off);
            int   oi = __shfl_xor_sync(0xffffffffu, bi, off);
            if (ov > bv || (ov == bv && oi < bi)) { bv = ov; bi = oi; }
        }
        if (lane == 0) s_mask[a] = (bi != 0);
    }
    __syncthreads();

    // decode boxes (one thread per anchor)
    if (tid < na) {
        int n = n0 + tid;
        const float* pp = priors + (size_t)n * 4;
        float p0 = pp[0], p1 = pp[1], p2 = pp[2], p3 = pp[3];
        float ph = p2 - p0, pw = p3 - p1;
        float pcy = p0 + 0.5f * ph, pcx = p1 + 0.5f * pw;
        const float* dd = deltas + ((size_t)b * N + n) * 4;
        float d0 = dd[0] * 0.1f, d1 = dd[1] * 0.1f;
        float d2 = dd[2] * 0.2f, d3 = dd[3] * 0.2f;
        float cy = d0 * ph + pcy, cx = d1 * pw + pcx;
        float h = expf(d2) * ph, w = expf(d3) * pw;
        float4 bx;
        bx.x = fminf(fmaxf(cy - h * 0.5f, 0.f), 1.f);
        bx.y = fminf(fmaxf(cx - w * 0.5f, 0.f), 1.f);
        bx.z = fminf(fmaxf(cy + h * 0.5f, 0.f), 1.f);
        bx.w = fminf(fmaxf(cx + w * 0.5f, 0.f), 1.f);
        g_boxes[(size_t)b * N + n] = bx;
        g_mask [(size_t)b * N + n] = (unsigned char)s_mask[tid];
    }

    // candidate collection (masked scores)
    for (int i = tid; i < tot; i += 256) {
        int a = i / C;
        if (!s_mask[a]) continue;
        float s = sm[i];
        if (s > 0.5f) {
            int c = i - a * C;
            atomicAdd(&s_cnt05[c], 1);
            if (s > THETA) {
                int col = b * C + c;
                int p = atomicAdd(&g_candCnt[col], 1);
                if (p < CAP) {
                    unsigned int n = (unsigned)(n0 + a);
                    g_cand[(size_t)col * CAP + p] =
                        ((unsigned long long)__float_as_uint(s) << 32) |
                        (0xFFFFFFFFu - n);
                }
            }
        }
    }
    __syncthreads();
    for (int c = tid; c < C; c += 256)
        if (s_cnt05[c]) atomicAdd(&g_tot05[b * C + c], s_cnt05[c]);
}

// ---------------- Phase B: per-(b,c) sorted-scan greedy NMS ----------------
__global__ __launch_bounds__(512) void phaseB(
    const float* __restrict__ labels, int B, int N, int C)
{
    int col = blockIdx.x;                 // b*C + c
    int b = col / C, c = col - b * C;
    int tid = threadIdx.x, lane = tid & 31, wid = tid >> 5;

    __shared__ unsigned long long keys[CAP];
    __shared__ float4 candBox[PREF];
    __shared__ float4 keptBox[KPC];
    __shared__ float keptS[KPC];
    __shared__ int keptNi[KPC];
    __shared__ int s_kept, s_fb;
    __shared__ unsigned long long s_wmax[16];
    __shared__ unsigned long long s_best;

    int rawCnt = g_candCnt[col];
    int cnt = min(rawCnt, CAP);
    int tot05 = g_tot05[col];

    for (int i = tid; i < cnt; i += 512)
        keys[i] = g_cand[(size_t)col * CAP + i];
    int P = 1; while (P < cnt) P <<= 1;
    for (int i = tid; i < P; i += 512)
        if (i >= cnt) keys[i] = 0ull;
    __syncthreads();

    // bitonic sort descending (key = score desc, anchor index asc)
    for (int k = 2; k <= P; k <<= 1) {
        for (int j = k >> 1; j > 0; j >>= 1) {
            for (int i = tid; i < P; i += 512) {
                int ixj = i ^ j;
                if (ixj > i) {
                    unsigned long long a = keys[i], bb = keys[ixj];
                    if (((i & k) != 0) ? (a > bb) : (a < bb)) {
                        keys[i] = bb; keys[ixj] = a;
                    }
                }
            }
            __syncthreads();
        }
    }

    // prefetch the first PREF candidate boxes
    for (int i = tid; i < cnt && i < PREF; i += 512) {
        unsigned int n = 0xFFFFFFFFu - (unsigned)(keys[i] & 0xFFFFFFFFull);
        candBox[i] = g_boxes[(size_t)b * N + n];
    }
    __syncthreads();

    // warp-0 sequential greedy scan
    if (wid == 0) {
        int kept = 0;
        for (int i = 0; i < cnt && kept < KPC; i++) {
            unsigned long long kk = keys[i];
            unsigned int n = 0xFFFFFFFFu - (unsigned)(kk & 0xFFFFFFFFull);
            float s = __uint_as_float((unsigned)(kk >> 32));
            float4 bb = (i < PREF) ? candBox[i] : g_boxes[(size_t)b * N + n];
            bool sup = false;
            for (int t = lane; t < kept; t += 32)
                if (iouf(keptBox[t], bb) > 0.5f) sup = true;
            sup = __any_sync(0xffffffffu, sup);
            if (!sup) {
                if (lane == 0) {
                    keptBox[kept] = bb; keptS[kept] = s; keptNi[kept] = (int)n;
                }
                kept++;
                __syncwarp();
            }
        }
        if (lane == 0) {
            s_kept = kept;
            s_fb = (rawCnt > CAP) || (kept < KPC && tot05 > cnt);
        }
    }
    __syncthreads();

    // exact fallback: full repeated-argmax greedy from scratch (never taken in
    // practice; guarantees exactness for any input)
    if (s_fb) {
        if (tid == 0) s_kept = 0;
        __syncthreads();
        for (int iter = 0; iter < KPC; iter++) {
            int kept = s_kept;
            unsigned long long best = 0ull;
            for (int n = tid; n < N; n += 512) {
                if (!g_mask[(size_t)b * N + n]) continue;
                float s = labels[((size_t)b * N + n) * C + c];
                if (s <= 0.5f) continue;
                unsigned long long key =
                    ((unsigned long long)__float_as_uint(s) << 32) |
                    (0xFFFFFFFFu - (unsigned)n);
                if (key <= best) continue;
                float4 bb = g_boxes[(size_t)b * N + n];
                bool sup = false;
                for (int t = 0; t < kept && !sup; t++) {
                    if (keptNi[t] == n) sup = true;
                    else if (iouf(keptBox[t], bb) > 0.5f) sup = true;
                }
                if (!sup) best = key;
            }
            for (int off = 16; off; off >>= 1) {
                unsigned long long o = __shfl_xor_sync(0xffffffffu, best, off);
                if (o > best) best = o;
            }
            if (lane == 0) s_wmax[wid] = best;
            __syncthreads();
            if (wid == 0) {
                unsigned long long v = (lane < 16) ? s_wmax[lane] : 0ull;
                for (int off = 8; off; off >>= 1) {
                    unsigned long long o = __shfl_xor_sync(0xffffffffu, v, off);
                    if (o > v) v = o;
                }
                if (lane == 0) s_best = v;
            }
            __syncthreads();
            if (s_best == 0ull) break;
            if (tid == 0) {
                unsigned long long kk = s_best;
                unsigned int n = 0xFFFFFFFFu - (unsigned)(kk & 0xFFFFFFFFull);
                keptBox[s_kept] = g_boxes[(size_t)b * N + n];
                keptS[s_kept] = __uint_as_float((unsigned)(kk >> 32));
                keptNi[s_kept] = (int)n;
                s_kept = s_kept + 1;
            }
            __syncthreads();
        }
        __syncthreads();
    }
    __syncthreads();

    int kept = s_kept;
    for (int k = tid; k < KPC; k += 512) {
        g_keptScore[(size_t)col * KPC + k] = (k < kept) ? keptS[k] : 0.f;
        g_keptN   [(size_t)col * KPC + k] = (k < kept) ? keptNi[k] : 0;
    }
}

// ---------------- Phase C: per-batch top-200 merge ----------------
__global__ __launch_bounds__(512) void phaseC(
    float* __restrict__ out, int B, int N, int C)
{
    int b = blockIdx.x;
    int M = C * KPC;                       // 4050
    __shared__ unsigned long long keys[4096];
    __shared__ int s_vc;
    int tid = threadIdx.x;
    int P = 1; while (P < M) P <<= 1;      // 4096

    for (int i = tid; i < P; i += 512) {
        unsigned long long k = 0ull;
        if (i < M) {
            float s = g_keptScore[(size_t)b * M + i];
            k = ((unsigned long long)__float_as_uint(s) << 32) |
                (0xFFFFFFFFu - (unsigned)i);
        }
        keys[i] = k;
    }
    if (tid == 0) s_vc = 0;
    __syncthreads();

    for (int k = 2; k <= P; k <<= 1) {
        for (int j = k >> 1; j > 0; j >>= 1) {
            for (int i = tid; i < P; i += 512) {
                int ixj = i ^ j;
                if (ixj > i) {
                    unsigned long long a = keys[i], bb = keys[ixj];
                    if (((i & k) != 0) ? (a > bb) : (a < bb)) {
                        keys[i] = bb; keys[ixj] = a;
                    }
                }
            }
            __syncthreads();
        }
    }

    float* outBoxes   = out;
    float* outScores  = out + (size_t)B * MAXTOT * 4;
    float* outClasses = outScores + (size_t)B * MAXTOT;
    float* outCount   = outClasses + (size_t)B * MAXTOT;

    if (tid < MAXTOT) {
        unsigned long long kk = keys[tid];
        float s = __uint_as_float((unsigned)(kk >> 32));
        unsigned flat = 0xFFFFFFFFu - (unsigned)(kk & 0xFFFFFFFFull);
        float4 bx = make_float4(0.f, 0.f, 0.f, 0.f);
        float cls = 0.f;
        if (s > 0.f) {
            int cc = flat / KPC;
            int n = g_keptN[(size_t)b * M + flat];
            bx = g_boxes[(size_t)b * N + n];
            cls = (float)cc;
            atomicAdd(&s_vc, 1);
        }
        size_t o = (size_t)b * MAXTOT + tid;
        outBoxes[o * 4 + 0] = bx.x;
        outBoxes[o * 4 + 1] = bx.y;
        outBoxes[o * 4 + 2] = bx.z;
        outBoxes[o * 4 + 3] = bx.w;
        outScores[o]  = s;
        outClasses[o] = cls;
    }
    __syncthreads();
    if (tid == 0) outCount[b] = (float)s_vc;
}

// ---------------- launch ----------------
extern "C" void kernel_launch(void* const* d_in, const int* in_sizes, int n_in,
                              void* d_out, int out_size) {
    const float* deltas = (const float*)d_in[0];   // pred_deltas (B,N,4)
    const float* labels = (const float*)d_in[1];   // pred_labels (B,N,C)
    const float* priors = (const float*)d_in[2];   // prior_boxes (N,4)

    int N = in_sizes[2] / 4;
    int B = in_sizes[0] / (4 * N);
    int C = in_sizes[1] / (B * N);

    int nz = B * C;
    zero_kernel<<<(nz + 255) / 256, 256>>>(nz);

    int tilesPerB = (N + 31) / 32;
    phaseA<<<B * tilesPerB, 256>>>(labels, deltas, priors, B, N, C);
    phaseB<<<B * C, 512>>>(labels, B, N, C);
    phaseC<<<B, 512>>>((float*)d_out, B, N, C);
}

// round 2
// speedup vs baseline: 1.1139x; 1.1139x over previous
#include <cuda_runtime.h>
#include <cstdint>

#define MAXB 16
#define MAXN 24564
#define MAXC 81
#define CAP  1024      // per-(b,c) candidate shortlist capacity
#define KPC  50        // MAX_PER_CLASS
#define MAXTOT 200
#define THETA 0.98f    // shortlist score threshold ( > SCORE_THR=0.5 )
#define PREF 256

typedef unsigned long long ull;

// ---------------- static device scratch ----------------
__device__ float4 g_boxes[MAXB * MAXN];
__device__ unsigned char g_mask[MAXB * MAXN];
__device__ ull g_cand[(size_t)MAXB * MAXC * CAP];
__device__ int g_candCnt[MAXB * MAXC];
__device__ float g_keptScore[MAXB * MAXC * KPC];
__device__ int   g_keptN[MAXB * MAXC * KPC];

__device__ __forceinline__ float iouf(float4 a, float4 b) {
    float iy1 = fmaxf(a.x, b.x);
    float ix1 = fmaxf(a.y, b.y);
    float iy2 = fminf(a.z, b.z);
    float ix2 = fminf(a.w, b.w);
    float inter = fmaxf(iy2 - iy1, 0.f) * fmaxf(ix2 - ix1, 0.f);
    float a0 = (a.z - a.x) * (a.w - a.y);
    float a1 = (b.z - b.x) * (b.w - b.y);
    return inter / (a0 + a1 - inter + 1e-8f);
}

__global__ void zero_kernel(int n) {
    int i = blockIdx.x * blockDim.x + threadIdx.x;
    if (i < n) g_candCnt[i] = 0;
}

// ---------------- Phase A: one warp per anchor ----------------
// Fused: argmax background mask + box decode + shortlist collection.
// No shared memory, no per-score atomics; labels read once, coalesced.
__global__ __launch_bounds__(256) void phaseA(
    const float* __restrict__ labels,   // (B,N,C)
    const float* __restrict__ deltas,   // (B,N,4)
    const float* __restrict__ priors,   // (N,4)
    int B, int N, int C)
{
    int wid = threadIdx.x >> 5, lane = threadIdx.x & 31;
    long long gw = (long long)blockIdx.x * 8 + wid;
    if (gw >= (long long)B * N) return;
    int b = (int)(gw / N);
    int n = (int)(gw - (long long)b * N);

    const float* L = labels + ((size_t)b * N + n) * C;
    int j0 = lane, j1 = lane + 32, j2 = lane + 64;
    float v0 = (j0 < C) ? L[j0] : -1e30f;
    float v1 = (j1 < C) ? L[j1] : -1e30f;
    float v2 = (j2 < C) ? L[j2] : -1e30f;

    // argmax with first-index tie-break (matches jnp.argmax)
    float bv = v0; int bi = j0;
    if (v1 > bv) { bv = v1; bi = j1; }
    if (v2 > bv) { bv = v2; bi = j2; }
    for (int off = 16; off; off >>= 1) {
        float ov = __shfl_xor_sync(0xffffffffu, bv, off);
        int   oi = __shfl_xor_sync(0xffffffffu, bi, off);
        if (ov > bv || (ov == bv && oi < bi)) { bv = ov; bi = oi; }
    }
    int mask = (bi != 0);

    if (lane == 0) {
        const float* pp = priors + (size_t)n * 4;
        float p0 = pp[0], p1 = pp[1], p2 = pp[2], p3 = pp[3];
        float ph = p2 - p0, pw = p3 - p1;
        float pcy = p0 + 0.5f * ph, pcx = p1 + 0.5f * pw;
        const float* dd = deltas + ((size_t)b * N + n) * 4;
        float d0 = dd[0] * 0.1f, d1 = dd[1] * 0.1f;
        float d2 = dd[2] * 0.2f, d3 = dd[3] * 0.2f;
        float cy = d0 * ph + pcy, cx = d1 * pw + pcx;
        float h = expf(d2) * ph, w = expf(d3) * pw;
        float4 bx;
        bx.x = fminf(fmaxf(cy - h * 0.5f, 0.f), 1.f);
        bx.y = fminf(fmaxf(cx - w * 0.5f, 0.f), 1.f);
        bx.z = fminf(fmaxf(cy + h * 0.5f, 0.f), 1.f);
        bx.w = fminf(fmaxf(cx + w * 0.5f, 0.f), 1.f);
        g_boxes[(size_t)b * N + n] = bx;
        g_mask [(size_t)b * N + n] = (unsigned char)mask;
    }

    if (mask) {
        ull tail = (ull)(0xFFFFFFFFu - (unsigned)n);
        if (j0 < C && v0 > THETA) {
            int col = b * C + j0;
            int p = atomicAdd(&g_candCnt[col], 1);
            if (p < CAP)
                g_cand[(size_t)col * CAP + p] = ((ull)__float_as_uint(v0) << 32) | tail;
        }
        if (j1 < C && v1 > THETA) {
            int col = b * C + j1;
            int p = atomicAdd(&g_candCnt[col], 1);
            if (p < CAP)
                g_cand[(size_t)col * CAP + p] = ((ull)__float_as_uint(v1) << 32) | tail;
        }
        if (j2 < C && v2 > THETA) {
            int col = b * C + j2;
            int p = atomicAdd(&g_candCnt[col], 1);
            if (p < CAP)
                g_cand[(size_t)col * CAP + p] = ((ull)__float_as_uint(v2) << 32) | tail;
        }
    }
}

// ---------------- Phase B: per-(b,c) sorted-scan greedy NMS ----------------
__global__ __launch_bounds__(128) void phaseB(
    const float* __restrict__ labels, int B, int N, int C)
{
    int col = blockIdx.x;                 // b*C + c
    int b = col / C, c = col - b * C;
    int tid = threadIdx.x, lane = tid & 31, wid = tid >> 5;

    __shared__ ull keys[CAP];
    __shared__ float4 candBox[PREF];
    __shared__ float4 keptBox[KPC];
    __shared__ float keptS[KPC];
    __shared__ int keptNi[KPC];
    __shared__ int s_kept, s_fb;
    __shared__ ull s_wmax[4];
    __shared__ ull s_best;

    int rawCnt = g_candCnt[col];
    int cnt = min(rawCnt, CAP);

    for (int i = tid; i < cnt; i += 128)
        keys[i] = g_cand[(size_t)col * CAP + i];
    int P = 1; while (P < cnt) P <<= 1;
    for (int i = tid; i < P; i += 128)
        if (i >= cnt) keys[i] = 0ull;
    __syncthreads();

    // bitonic sort descending (score desc, anchor index asc)
    for (int k = 2; k <= P; k <<= 1) {
        for (int j = k >> 1; j > 0; j >>= 1) {
            for (int i = tid; i < P; i += 128) {
                int ixj = i ^ j;
                if (ixj > i) {
                    ull a = keys[i], bb = keys[ixj];
                    if (((i & k) != 0) ? (a > bb) : (a < bb)) {
                        keys[i] = bb; keys[ixj] = a;
                    }
                }
            }
            __syncthreads();
        }
    }

    for (int i = tid; i < cnt && i < PREF; i += 128) {
        unsigned int n = 0xFFFFFFFFu - (unsigned)(keys[i] & 0xFFFFFFFFull);
        candBox[i] = g_boxes[(size_t)b * N + n];
    }
    __syncthreads();

    // warp-0 sequential greedy scan (equivalent to repeated-argmax greedy)
    if (wid == 0) {
        int kept = 0;
        for (int i = 0; i < cnt && kept < KPC; i++) {
            ull kk = keys[i];
            unsigned int n = 0xFFFFFFFFu - (unsigned)(kk & 0xFFFFFFFFull);
            float s = __uint_as_float((unsigned)(kk >> 32));
            float4 bb = (i < PREF) ? candBox[i] : g_boxes[(size_t)b * N + n];
            bool sup = false;
            for (int t = lane; t < kept; t += 32)
                if (iouf(keptBox[t], bb) > 0.5f) sup = true;
            sup = __any_sync(0xffffffffu, sup);
            if (!sup) {
                if (lane == 0) {
                    keptBox[kept] = bb; keptS[kept] = s; keptNi[kept] = (int)n;
                }
                kept++;
                __syncwarp();
            }
        }
        if (lane == 0) {
            s_kept = kept;
            // exact-fallback trigger: shortlist may have been insufficient
            s_fb = (rawCnt > CAP) || (kept < KPC);
        }
    }
    __syncthreads();

    // exact fallback: full repeated-argmax greedy over all scores > 0.5
    // (statistically never taken on this workload; guarantees exactness)
    if (s_fb) {
        if (tid == 0) s_kept = 0;
        __syncthreads();
        for (int iter = 0; iter < KPC; iter++) {
            int kept = s_kept;
            ull best = 0ull;
            for (int n = tid; n < N; n += 128) {
                if (!g_mask[(size_t)b * N + n]) continue;
                float s = labels[((size_t)b * N + n) * C + c];
                if (s <= 0.5f) continue;
                ull key = ((ull)__float_as_uint(s) << 32) |
                          (0xFFFFFFFFu - (unsigned)n);
                if (key <= best) continue;
                float4 bb = g_boxes[(size_t)b * N + n];
                bool sup = false;
                for (int t = 0; t < kept && !sup; t++) {
                    if (keptNi[t] == n) sup = true;
                    else if (iouf(keptBox[t], bb) > 0.5f) sup = true;
                }
                if (!sup) best = key;
            }
            for (int off = 16; off; off >>= 1) {
                ull o = __shfl_xor_sync(0xffffffffu, best, off);
                if (o > best) best = o;
            }
            if (lane == 0) s_wmax[wid] = best;
            __syncthreads();
            if (wid == 0) {
                ull v = (lane < 4) ? s_wmax[lane] : 0ull;
                for (int off = 2; off; off >>= 1) {
                    ull o = __shfl_xor_sync(0xffffffffu, v, off);
                    if (o > v) v = o;
                }
                if (lane == 0) s_best = v;
            }
            __syncthreads();
            if (s_best == 0ull) break;
            if (tid == 0) {
                ull kk = s_best;
                unsigned int n = 0xFFFFFFFFu - (unsigned)(kk & 0xFFFFFFFFull);
                keptBox[s_kept] = g_boxes[(size_t)b * N + n];
                keptS[s_kept] = __uint_as_float((unsigned)(kk >> 32));
                keptNi[s_kept] = (int)n;
                s_kept = s_kept + 1;
            }
            __syncthreads();
        }
        __syncthreads();
    }
    __syncthreads();

    int kept = s_kept;
    for (int k = tid; k < KPC; k += 128) {
        g_keptScore[(size_t)col * KPC + k] = (k < kept) ? keptS[k] : 0.f;
        g_keptN   [(size_t)col * KPC + k] = (k < kept) ? keptNi[k] : 0;
    }
}

// ---------------- Phase C: 81-way tournament merge (per-class lists sorted) ----
__global__ __launch_bounds__(256) void phaseC(
    float* __restrict__ out, int B, int N, int C)
{
    int b = blockIdx.x;
    int M = C * KPC;                       // 4050
    __shared__ ull sk[MAXC * KPC];
    __shared__ ull outk[MAXTOT];
    __shared__ int s_vc;
    int tid = threadIdx.x;

    for (int i = tid; i < M; i += 256) {
        float s = g_keptScore[(size_t)b * M + i];
        sk[i] = ((ull)__float_as_uint(s) << 32) | (0xFFFFFFFFu - (unsigned)i);
    }
    if (tid == 0) s_vc = 0;
    __syncthreads();

    // single-warp 81-way merge; each lane owns up to 3 class lists
    if (tid < 32) {
        int lane = tid;
        ull cur[3]; int pos[3]; int base[3];
        #pragma unroll
        for (int r = 0; r < 3; r++) {
            int c = lane + 32 * r;
            base[r] = c * KPC; pos[r] = 0;
            cur[r] = (c < C) ? sk[c * KPC] : 0ull;
        }
        for (int it = 0; it < MAXTOT; it++) {
            ull m = cur[0]; int mr = 0;
            if (cur[1] > m) { m = cur[1]; mr = 1; }
            if (cur[2] > m) { m = cur[2]; mr = 2; }
            ull w = m;
            for (int off = 16; off; off >>= 1) {
                ull o = __shfl_xor_sync(0xffffffffu, w, off);
                if (o > w) w = o;
            }
            if (lane == 0) outk[it] = w;
            unsigned bal = __ballot_sync(0xffffffffu, (m == w) && (w != 0ull));
            if (bal) {
                int winner = __ffs(bal) - 1;
                if (lane == winner) {
                    pos[mr]++;
                    cur[mr] = (pos[mr] < KPC) ? sk[base[mr] + pos[mr]] : 0ull;
                }
            }
        }
    }
    __syncthreads();

    float* outBoxes   = out;
    float* outScores  = out + (size_t)B * MAXTOT * 4;
    float* outClasses = outScores + (size_t)B * MAXTOT;
    float* outCount   = outClasses + (size_t)B * MAXTOT;

    if (tid < MAXTOT) {
        ull kk = outk[tid];
        float s = __uint_as_float((unsigned)(kk >> 32));
        unsigned flat = 0xFFFFFFFFu - (unsigned)(kk & 0xFFFFFFFFull);
        float4 bx = make_float4(0.f, 0.f, 0.f, 0.f);
        float cls = 0.f;
        if (s > 0.f) {
            int n = g_keptN[(size_t)b * M + flat];
            bx = g_boxes[(size_t)b * N + n];
            cls = (float)(flat / KPC);
            atomicAdd(&s_vc, 1);
        }
        size_t o = (size_t)b * MAXTOT + tid;
        outBoxes[o * 4 + 0] = bx.x;
        outBoxes[o * 4 + 1] = bx.y;
        outBoxes[o * 4 + 2] = bx.z;
        outBoxes[o * 4 + 3] = bx.w;
        outScores[o]  = s;
        outClasses[o] = cls;
    }
    __syncthreads();
    if (tid == 0) outCount[b] = (float)s_vc;
}

// ---------------- launch ----------------
extern "C" void kernel_launch(void* const* d_in, const int* in_sizes, int n_in,
                              void* d_out, int out_size) {
    const float* deltas = (const float*)d_in[0];   // pred_deltas (B,N,4)
    const float* labels = (const float*)d_in[1];   // pred_labels (B,N,C)
    const float* priors = (const float*)d_in[2];   // prior_boxes (N,4)

    int N = in_sizes[2] / 4;
    int B = in_sizes[0] / (4 * N);
    int C = in_sizes[1] / (B * N);

    int nz = B * C;
    zero_kernel<<<(nz + 255) / 256, 256>>>(nz);

    long long anchors = (long long)B * N;
    int blocksA = (int)((anchors + 7) / 8);
    phaseA<<<blocksA, 256>>>(labels, deltas, priors, B, N, C);
    phaseB<<<B * C, 128>>>(labels, B, N, C);
    phaseC<<<B, 256>>>((float*)d_out, B, N, C);
}

// round 3
// speedup vs baseline: 1.3333x; 1.1970x over previous
#include <cuda_runtime.h>
#include <cstdint>

#define MAXB 16
#define MAXN 24564
#define MAXC 81
#define CAP  1024      // per-(b,c) candidate shortlist capacity
#define KPC  50        // MAX_PER_CLASS
#define MAXTOT 200
#define THETA 0.98f    // shortlist score threshold ( > SCORE_THR=0.5 )
#define TH2   0.995f   // tier-1 selection threshold inside shortlist
#define SELB  256      // phaseB tier-1 selection capacity (pow2)
#define SELC  512      // phaseC selection capacity (pow2)
#define NBIN  512

typedef unsigned long long ull;

// ---------------- static device scratch ----------------
__device__ float4 g_boxes[MAXB * MAXN];
__device__ unsigned char g_mask[MAXB * MAXN];
__device__ ull g_cand[(size_t)MAXB * MAXC * CAP];
__device__ int g_candCnt[MAXB * MAXC];
__device__ float g_keptScore[MAXB * MAXC * KPC];
__device__ int   g_keptN[MAXB * MAXC * KPC];

__device__ __forceinline__ float iouf(float4 a, float4 b) {
    float iy1 = fmaxf(a.x, b.x);
    float ix1 = fmaxf(a.y, b.y);
    float iy2 = fminf(a.z, b.z);
    float ix2 = fminf(a.w, b.w);
    float inter = fmaxf(iy2 - iy1, 0.f) * fmaxf(ix2 - ix1, 0.f);
    float a0 = (a.z - a.x) * (a.w - a.y);
    float a1 = (b.z - b.x) * (b.w - b.y);
    return inter / (a0 + a1 - inter + 1e-8f);
}

// bitonic sort descending, executed by all nthreads threads, P = pow2
__device__ __forceinline__ void bitonic_desc(ull* a, int P, int tid, int nthreads) {
    for (int k = 2; k <= P; k <<= 1) {
        for (int j = k >> 1; j > 0; j >>= 1) {
            for (int i = tid; i < P; i += nthreads) {
                int ixj = i ^ j;
                if (ixj > i) {
                    ull x = a[i], y = a[ixj];
                    if (((i & k) != 0) ? (x > y) : (x < y)) { a[i] = y; a[ixj] = x; }
                }
            }
            __syncthreads();
        }
    }
}

// ---------------- Phase A: one warp per anchor ----------------
__global__ __launch_bounds__(256) void phaseA(
    const float* __restrict__ labels,   // (B,N,C)
    const float* __restrict__ deltas,   // (B,N,4)
    const float* __restrict__ priors,   // (N,4)
    int N, int C)
{
    int wid = threadIdx.x >> 5, lane = threadIdx.x & 31;
    int n = blockIdx.x * 8 + wid;
    int b = blockIdx.y;
    if (n >= N) return;

    const float* L = labels + ((size_t)b * N + n) * C;
    int j0 = lane, j1 = lane + 32, j2 = lane + 64;
    float v0 = (j0 < C) ? L[j0] : -1e30f;
    float v1 = (j1 < C) ? L[j1] : -1e30f;
    float v2 = (j2 < C) ? L[j2] : -1e30f;

    // argmax with first-index tie-break (matches jnp.argmax)
    float bv = v0; int bi = j0;
    if (v1 > bv) { bv = v1; bi = j1; }
    if (v2 > bv) { bv = v2; bi = j2; }
    for (int off = 16; off; off >>= 1) {
        float ov = __shfl_xor_sync(0xffffffffu, bv, off);
        int   oi = __shfl_xor_sync(0xffffffffu, bi, off);
        if (ov > bv || (ov == bv && oi < bi)) { bv = ov; bi = oi; }
    }
    int mask = (bi != 0);

    if (lane == 0) {
        const float* pp = priors + (size_t)n * 4;
        float p0 = pp[0], p1 = pp[1], p2 = pp[2], p3 = pp[3];
        float ph = p2 - p0, pw = p3 - p1;
        float pcy = p0 + 0.5f * ph, pcx = p1 + 0.5f * pw;
        const float* dd = deltas + ((size_t)b * N + n) * 4;
        float d0 = dd[0] * 0.1f, d1 = dd[1] * 0.1f;
        float d2 = dd[2] * 0.2f, d3 = dd[3] * 0.2f;
        float cy = d0 * ph + pcy, cx = d1 * pw + pcx;
        float h = expf(d2) * ph, w = expf(d3) * pw;
        float4 bx;
        bx.x = fminf(fmaxf(cy - h * 0.5f, 0.f), 1.f);
        bx.y = fminf(fmaxf(cx - w * 0.5f, 0.f), 1.f);
        bx.z = fminf(fmaxf(cy + h * 0.5f, 0.f), 1.f);
        bx.w = fminf(fmaxf(cx + w * 0.5f, 0.f), 1.f);
        g_boxes[(size_t)b * N + n] = bx;
        g_mask [(size_t)b * N + n] = (unsigned char)mask;
    }

    if (mask) {
        ull tail = (ull)(0xFFFFFFFFu - (unsigned)n);
        if (j0 < C && v0 > THETA) {
            int col = b * C + j0;
            int p = atomicAdd(&g_candCnt[col], 1);
            if (p < CAP)
                g_cand[(size_t)col * CAP + p] = ((ull)__float_as_uint(v0) << 32) | tail;
        }
        if (j1 < C && v1 > THETA) {
            int col = b * C + j1;
            int p = atomicAdd(&g_candCnt[col], 1);
            if (p < CAP)
                g_cand[(size_t)col * CAP + p] = ((ull)__float_as_uint(v1) << 32) | tail;
        }
        if (j2 < C && v2 > THETA) {
            int col = b * C + j2;
            int p = atomicAdd(&g_candCnt[col], 1);
            if (p < CAP)
                g_cand[(size_t)col * CAP + p] = ((ull)__float_as_uint(v2) << 32) | tail;
        }
    }
}

// warp-0 sequential greedy scan over a descending-sorted array. Returns kept.
__device__ __forceinline__ int nms_scan(
    const ull* arr, int n, const float4* candBox, int prefN,
    size_t bBase, int lane,
    float4* keptBox, float* keptS, int* keptNi)
{
    int kept = 0;
    for (int i = 0; i < n && kept < KPC; i++) {
        ull kk = arr[i];
        unsigned nn = 0xFFFFFFFFu - (unsigned)(kk & 0xFFFFFFFFull);
        float4 bb = (i < prefN) ? candBox[i] : g_boxes[bBase + nn];
        bool sup = false;
        for (int t = lane; t < kept; t += 32)
            if (iouf(keptBox[t], bb) > 0.5f) sup = true;
        if (__any_sync(0xffffffffu, sup)) continue;
        if (lane == 0) {
            keptBox[kept] = bb;
            keptS[kept] = __uint_as_float((unsigned)(kk >> 32));
            keptNi[kept] = (int)nn;
        }
        kept++;
        __syncwarp();
    }
    return kept;
}

// ---------------- Phase B: per-(b,c) tiered sorted-scan greedy NMS ----------------
__global__ __launch_bounds__(128) void phaseB(
    const float* __restrict__ labels, int B, int N, int C)
{
    int col = blockIdx.x;                 // b*C + c
    int b = col / C, c = col - b * C;
    int tid = threadIdx.x, lane = tid & 31, wid = tid >> 5;

    __shared__ ull keys[CAP];
    __shared__ ull sel[SELB];
    __shared__ float4 candBox[SELB];
    __shared__ float4 keptBox[KPC];
    __shared__ float keptS[KPC];
    __shared__ int keptNi[KPC];
    __shared__ int s_selCnt, s_kept, s_t2, s_t3;
    __shared__ ull s_wmax[4];
    __shared__ ull s_best;

    int rawCnt = g_candCnt[col];
    int cnt = min(rawCnt, CAP);
    size_t bBase = (size_t)b * N;

    for (int i = tid; i < cnt; i += 128)
        keys[i] = g_cand[(size_t)col * CAP + i];
    if (tid == 0) { s_selCnt = 0; s_t2 = 0; s_t3 = 0; }
    __syncthreads();

    // ---- tier 1: select keys with score >= TH2, sort 256, scan ----
    const ull T2 = ((ull)__float_as_uint(TH2)) << 32;
    for (int i = tid; i < cnt; i += 128) {
        ull k = keys[i];
        if (k >= T2) {
            int p = atomicAdd(&s_selCnt, 1);
            if (p < SELB) sel[p] = k;
        }
    }
    __syncthreads();
    int selCnt = s_selCnt;
    bool t1ok = (selCnt <= SELB);
    int m = min(selCnt, SELB);

    if (t1ok) {
        for (int i = tid; i < SELB; i += 128)
            if (i >= m) sel[i] = 0ull;
        __syncthreads();
        bitonic_desc(sel, SELB, tid, 128);
        for (int i = tid; i < m; i += 128) {
            unsigned nn = 0xFFFFFFFFu - (unsigned)(sel[i] & 0xFFFFFFFFull);
            candBox[i] = g_boxes[bBase + nn];
        }
        __syncthreads();
        if (wid == 0) {
            int kept = nms_scan(sel, m, candBox, m, bBase, lane, keptBox, keptS, keptNi);
            if (lane == 0) {
                s_kept = kept;
                s_t2 = (kept < KPC && m < cnt);   // need sub-TH2 candidates
            }
        }
    } else {
        if (tid == 0) s_t2 = 1;                   // selection overflow -> full sort
    }
    __syncthreads();

    // ---- tier 2: full bitonic over entire shortlist (rare) ----
    if (s_t2) {
        int P = 1; while (P < cnt) P <<= 1;
        if (P < 2) P = 2;
        for (int i = tid; i < P; i += 128)
            if (i >= cnt) keys[i] = 0ull;
        __syncthreads();
        bitonic_desc(keys, P, tid, 128);
        for (int i = tid; i < cnt && i < SELB; i += 128) {
            unsigned nn = 0xFFFFFFFFu - (unsigned)(keys[i] & 0xFFFFFFFFull);
            candBox[i] = g_boxes[bBase + nn];
        }
        __syncthreads();
        if (wid == 0) {
            int kept = nms_scan(keys, cnt, candBox, min(cnt, SELB), bBase, lane,
                                keptBox, keptS, keptNi);
            if (lane == 0) s_kept = kept;
        }
        __syncthreads();
    }

    if (tid == 0) s_t3 = (rawCnt > CAP) || (s_kept < KPC);
    __syncthreads();

    // ---- tier 3: exact repeated-argmax greedy over all scores > 0.5 ----
    // (statistically never taken; guarantees exactness on any input)
    if (s_t3) {
        if (tid == 0) s_kept = 0;
        __syncthreads();
        for (int iter = 0; iter < KPC; iter++) {
            int kept = s_kept;
            ull best = 0ull;
            for (int n = tid; n < N; n += 128) {
                if (!g_mask[bBase + n]) continue;
                float s = labels[(bBase + n) * C + c];
                if (s <= 0.5f) continue;
                ull key = ((ull)__float_as_uint(s) << 32) |
                          (0xFFFFFFFFu - (unsigned)n);
                if (key <= best) continue;
                float4 bb = g_boxes[bBase + n];
                bool sup = false;
                for (int t = 0; t < kept && !sup; t++) {
                    if (keptNi[t] == n) sup = true;
                    else if (iouf(keptBox[t], bb) > 0.5f) sup = true;
                }
                if (!sup) best = key;
            }
            for (int off = 16; off; off >>= 1) {
                ull o = __shfl_xor_sync(0xffffffffu, best, off);
                if (o > best) best = o;
            }
            if (lane == 0) s_wmax[wid] = best;
            __syncthreads();
            if (wid == 0) {
                ull v = (lane < 4) ? s_wmax[lane] : 0ull;
                for (int off = 2; off; off >>= 1) {
                    ull o = __shfl_xor_sync(0xffffffffu, v, off);
                    if (o > v) v = o;
                }
                if (lane == 0) s_best = v;
            }
            __syncthreads();
            if (s_best == 0ull) break;
            if (tid == 0) {
                ull kk = s_best;
                unsigned nn = 0xFFFFFFFFu - (unsigned)(kk & 0xFFFFFFFFull);
                keptBox[s_kept] = g_boxes[bBase + nn];
                keptS[s_kept] = __uint_as_float((unsigned)(kk >> 32));
                keptNi[s_kept] = (int)nn;
                s_kept = s_kept + 1;
            }
            __syncthreads();
        }
        __syncthreads();
    }

    int kept = s_kept;
    for (int k = tid; k < KPC; k += 128) {
        g_keptScore[(size_t)col * KPC + k] = (k < kept) ? keptS[k] : 0.f;
        g_keptN   [(size_t)col * KPC + k] = (k < kept) ? keptNi[k] : 0;
    }
}

// ---------------- Phase C: histogram top-200 selection + small sort ----------------
__global__ __launch_bounds__(256) void phaseC(
    float* __restrict__ out, int B, int N, int C)
{
    int b = blockIdx.x;
    int M = C * KPC;                       // 4050
    __shared__ ull sk[4096];
    __shared__ ull sel[SELC];
    __shared__ int hist[NBIN];
    __shared__ int s_cnt, s_thr, s_fb;
    int tid = threadIdx.x;

    // reset shortlist counters for the next replay (phaseB already consumed them)
    for (int i = tid; i < C; i += 256) g_candCnt[b * C + i] = 0;

    for (int i = tid; i < 4096; i += 256) {
        ull k = 0ull;
        if (i < M) {
            float s = g_keptScore[(size_t)b * M + i];
            k = ((ull)__float_as_uint(s) << 32) | (0xFFFFFFFFu - (unsigned)i);
        }
        sk[i] = k;
    }
    for (int i = tid; i < NBIN; i += 256) hist[i] = 0;
    if (tid == 0) { s_cnt = 0; s_thr = -1; s_fb = 0; }
    __syncthreads();

    // histogram over monotone score-bit bins covering [0.9975, 1.0]
    const unsigned LOu = __float_as_uint(0.9975f);
    for (int i = tid; i < M; i += 256) {
        unsigned fb = (unsigned)(sk[i] >> 32);
        int d = (int)(fb - LOu);
        int bin = (d < 0) ? 0 : min(NBIN - 1, d >> 7);
        atomicAdd(&hist[bin], 1);
    }
    __syncthreads();

    // inclusive suffix-sum (Hillis-Steele), 2 bins per thread
    for (int off = 1; off < NBIN; off <<= 1) {
        int v0 = hist[tid]       + ((tid + off < NBIN) ? hist[tid + off] : 0);
        int i1 = tid + 256;
        int v1 = hist[i1]        + ((i1 + off < NBIN) ? hist[i1 + off] : 0);
        __syncthreads();
        hist[tid] = v0; hist[i1] = v1;
        __syncthreads();
    }
    // threshold bin: largest t with suffix>=MAXTOT
    for (int t = tid; t < NBIN; t += 256)
        if (hist[t] >= MAXTOT && (t == NBIN - 1 || hist[t + 1] < MAXTOT)) s_thr = t;
    __syncthreads();
    int thr = s_thr;
    if (thr <= 0 || hist[thr] > SELC) { if (tid == 0) s_fb = 1; }
    __syncthreads();

    int nsel = 0;
    if (!s_fb) {
        for (int i = tid; i < M; i += 256) {
            unsigned fb = (unsigned)(sk[i] >> 32);
            int d = (int)(fb - LOu);
            int bin = (d < 0) ? 0 : min(NBIN - 1, d >> 7);
            if (bin >= thr) {
                int p = atomicAdd(&s_cnt, 1);
                if (p < SELC) sel[p] = sk[i];
            }
        }
        __syncthreads();
        nsel = s_cnt;
        for (int i = tid; i < SELC; i += 256)
            if (i >= nsel) sel[i] = 0ull;
        __syncthreads();
        bitonic_desc(sel, SELC, tid, 256);
    } else {
        // exact fallback: full sort of all 4096 keys
        bitonic_desc(sk, 4096, tid, 256);
    }

    const ull* src = s_fb ? sk : sel;

    float* outBoxes   = out;
    float* outScores  = out + (size_t)B * MAXTOT * 4;
    float* outClasses = outScores + (size_t)B * MAXTOT;
    float* outCount   = outClasses + (size_t)B * MAXTOT;

    int validFlag = 0;
    if (tid < MAXTOT) {
        ull kk = src[tid];
        float s = __uint_as_float((unsigned)(kk >> 32));
        unsigned flat = 0xFFFFFFFFu - (unsigned)(kk & 0xFFFFFFFFull);
        float4 bx = make_float4(0.f, 0.f, 0.f, 0.f);
        float cls = 0.f;
        if (s > 0.f) {
            int n = g_keptN[(size_t)b * M + flat];
            bx = g_boxes[(size_t)b * N + n];
            cls = (float)(flat / KPC);
            validFlag = 1;
        }
        size_t o = (size_t)b * MAXTOT + tid;
        outBoxes[o * 4 + 0] = bx.x;
        outBoxes[o * 4 + 1] = bx.y;
        outBoxes[o * 4 + 2] = bx.z;
        outBoxes[o * 4 + 3] = bx.w;
        outScores[o]  = s;
        outClasses[o] = cls;
    }
    int vc = __syncthreads_count(validFlag);
    if (tid == 0) outCount[b] = (float)vc;
}

// ---------------- launch ----------------
extern "C" void kernel_launch(void* const* d_in, const int* in_sizes, int n_in,
                              void* d_out, int out_size) {
    const float* deltas = (const float*)d_in[0];   // pred_deltas (B,N,4)
    const float* labels = (const float*)d_in[1];   // pred_labels (B,N,C)
    const float* priors = (const float*)d_in[2];   // prior_boxes (N,4)

    int N = in_sizes[2] / 4;
    int B = in_sizes[0] / (4 * N);
    int C = in_sizes[1] / (B * N);

    dim3 gA((N + 7) / 8, B);
    phaseA<<<gA, 256>>>(labels, deltas, priors, N, C);
    phaseB<<<B * C, 128>>>(labels, B, N, C);
    phaseC<<<B, 256>>>((float*)d_out, B, N, C);
}

// round 4
// speedup vs baseline: 1.5505x; 1.1628x over previous
#include <cuda_runtime.h>
#include <cstdint>

#define MAXB 16
#define MAXN 24564
#define MAXC 81
#define CAP  1024      // per-(b,c) candidate shortlist capacity
#define KPC  50        // MAX_PER_CLASS
#define MAXTOT 200
#define THETA 0.98f    // shortlist score threshold ( > SCORE_THR=0.5 )
#define TH2   0.995f   // tier-1 selection threshold inside shortlist
#define SELB  256      // phaseB tier-1 selection capacity (pow2)
#define SELC  512      // phaseC selection capacity (pow2)
#define NBIN  512
#define TILE  32       // anchors per phaseA block

typedef unsigned long long ull;

// ---------------- static device scratch ----------------
__device__ float4 g_boxes[MAXB * MAXN];
__device__ unsigned char g_mask[MAXB * MAXN];
__device__ ull g_cand[(size_t)MAXB * MAXC * CAP];
__device__ int g_candCnt[MAXB * MAXC];
__device__ float g_keptScore[MAXB * MAXC * KPC];
__device__ int   g_keptN[MAXB * MAXC * KPC];

__device__ __forceinline__ float iouf(float4 a, float4 b) {
    float iy1 = fmaxf(a.x, b.x);
    float ix1 = fmaxf(a.y, b.y);
    float iy2 = fminf(a.z, b.z);
    float ix2 = fminf(a.w, b.w);
    float inter = fmaxf(iy2 - iy1, 0.f) * fmaxf(ix2 - ix1, 0.f);
    float a0 = (a.z - a.x) * (a.w - a.y);
    float a1 = (b.z - b.x) * (b.w - b.y);
    return inter / (a0 + a1 - inter + 1e-8f);
}

__device__ __forceinline__ void bitonic_desc(ull* a, int P, int tid, int nthreads) {
    for (int k = 2; k <= P; k <<= 1) {
        for (int j = k >> 1; j > 0; j >>= 1) {
            for (int i = tid; i < P; i += nthreads) {
                int ixj = i ^ j;
                if (ixj > i) {
                    ull x = a[i], y = a[ixj];
                    if (((i & k) != 0) ? (x > y) : (x < y)) { a[i] = y; a[ixj] = x; }
                }
            }
            __syncthreads();
        }
    }
}

// ---------------- Phase A v3: smem-staged tile, 8 threads per anchor ----------------
__global__ __launch_bounds__(256) void phaseA(
    const float* __restrict__ labels,   // (B,N,C)
    const float* __restrict__ deltas,   // (B,N,4)
    const float* __restrict__ priors,   // (N,4)
    int N, int C)
{
    __shared__ __align__(16) float sL[TILE * MAXC];

    int tid = threadIdx.x;
    int b = blockIdx.y;
    int n0 = blockIdx.x * TILE;
    int na = min(TILE, N - n0);
    size_t bBase = (size_t)b * N;

    // --- decode (independent of labels; float4-native, coalesced) ---
    if (tid < na) {
        int n = n0 + tid;
        float4 pr = ((const float4*)priors)[n];
        float4 dd = ((const float4*)deltas)[bBase + n];
        float ph = pr.z - pr.x, pw = pr.w - pr.y;
        float pcy = pr.x + 0.5f * ph, pcx = pr.y + 0.5f * pw;
        float d0 = dd.x * 0.1f, d1 = dd.y * 0.1f;
        float d2 = dd.z * 0.2f, d3 = dd.w * 0.2f;
        float cy = d0 * ph + pcy, cx = d1 * pw + pcx;
        float h = expf(d2) * ph, w = expf(d3) * pw;
        float4 bx;
        bx.x = fminf(fmaxf(cy - h * 0.5f, 0.f), 1.f);
        bx.y = fminf(fmaxf(cx - w * 0.5f, 0.f), 1.f);
        bx.z = fminf(fmaxf(cy + h * 0.5f, 0.f), 1.f);
        bx.w = fminf(fmaxf(cx + w * 0.5f, 0.f), 1.f);
        g_boxes[bBase + n] = bx;
    }

    // --- stage labels tile into smem (float4 when aligned) ---
    const float* base = labels + (bBase + n0) * (size_t)C;
    int totF = na * C;
    if ((((uintptr_t)base) & 15) == 0) {
        int tot4 = totF >> 2;
        const float4* b4 = (const float4*)base;
        float4* s4 = (float4*)sL;
        for (int i = tid; i < tot4; i += 256) s4[i] = b4[i];
        for (int i = (tot4 << 2) + tid; i < totF; i += 256) sL[i] = base[i];
    } else {
        for (int i = tid; i < totF; i += 256) sL[i] = base[i];
    }
    __syncthreads();

    // --- argmax: 8 threads per anchor; collect >THETA bitmask along the way ---
    int g = tid >> 3;          // anchor within tile
    int m = tid & 7;           // member within group
    float bv = -1e30f; int bi = 0x7fffffff;
    unsigned cb = 0;
    if (g < na) {
        const float* row = sL + g * C;
        int k = 0;
        for (int c = m; c < C; c += 8, k++) {
            float v = row[c];
            if (v > bv) { bv = v; bi = c; }
            if (v > THETA) cb |= (1u << k);
        }
    }
    // reduce within 8-lane group (xor offsets stay inside the group)
    for (int off = 4; off; off >>= 1) {
        float ov = __shfl_xor_sync(0xffffffffu, bv, off);
        int   oi = __shfl_xor_sync(0xffffffffu, bi, off);
        if (ov > bv || (ov == bv && oi < bi)) { bv = ov; bi = oi; }
    }
    int mask = (bi != 0);

    if (g < na) {
        if (m == 0) g_mask[bBase + n0 + g] = (unsigned char)mask;
        if (mask && cb) {
            unsigned tail = 0xFFFFFFFFu - (unsigned)(n0 + g);
            const float* row = sL + g * C;
            while (cb) {
                int k = __ffs(cb) - 1; cb &= cb - 1;
                int c = m + (k << 3);
                float v = row[c];
                int col = b * C + c;
                int p = atomicAdd(&g_candCnt[col], 1);
                if (p < CAP)
                    g_cand[(size_t)col * CAP + p] =
                        ((ull)__float_as_uint(v) << 32) | (ull)tail;
            }
        }
    }
}

// warp-0 sequential greedy scan over a descending-sorted array. Returns kept.
__device__ __forceinline__ int nms_scan(
    const ull* arr, int n, const float4* candBox, int prefN,
    size_t bBase, int lane,
    float4* keptBox, float* keptS, int* keptNi)
{
    int kept = 0;
    for (int i = 0; i < n && kept < KPC; i++) {
        ull kk = arr[i];
        unsigned nn = 0xFFFFFFFFu - (unsigned)(kk & 0xFFFFFFFFull);
        float4 bb = (i < prefN) ? candBox[i] : g_boxes[bBase + nn];
        bool sup = false;
        for (int t = lane; t < kept; t += 32)
            if (iouf(keptBox[t], bb) > 0.5f) sup = true;
        if (__any_sync(0xffffffffu, sup)) continue;
        if (lane == 0) {
            keptBox[kept] = bb;
            keptS[kept] = __uint_as_float((unsigned)(kk >> 32));
            keptNi[kept] = (int)nn;
        }
        kept++;
        __syncwarp();
    }
    return kept;
}

// ---------------- Phase B: per-(b,c) tiered sorted-scan greedy NMS ----------------
__global__ __launch_bounds__(128) void phaseB(
    const float* __restrict__ labels, int B, int N, int C)
{
    int col = blockIdx.x;                 // b*C + c
    int b = col / C, c = col - b * C;
    int tid = threadIdx.x, lane = tid & 31, wid = tid >> 5;

    __shared__ ull keys[CAP];
    __shared__ ull sel[SELB];
    __shared__ float4 candBox[SELB];
    __shared__ float4 keptBox[KPC];
    __shared__ float keptS[KPC];
    __shared__ int keptNi[KPC];
    __shared__ int s_selCnt, s_kept, s_t2, s_t3;
    __shared__ ull s_wmax[4];
    __shared__ ull s_best;

    int rawCnt = g_candCnt[col];
    int cnt = min(rawCnt, CAP);
    size_t bBase = (size_t)b * N;

    for (int i = tid; i < cnt; i += 128)
        keys[i] = g_cand[(size_t)col * CAP + i];
    if (tid == 0) { s_selCnt = 0; s_t2 = 0; s_t3 = 0; }
    __syncthreads();

    // ---- tier 1: select keys with score >= TH2, sort 256, scan ----
    const ull T2 = ((ull)__float_as_uint(TH2)) << 32;
    for (int i = tid; i < cnt; i += 128) {
        ull k = keys[i];
        if (k >= T2) {
            int p = atomicAdd(&s_selCnt, 1);
            if (p < SELB) sel[p] = k;
        }
    }
    __syncthreads();
    int selCnt = s_selCnt;
    bool t1ok = (selCnt <= SELB);
    int m = min(selCnt, SELB);

    if (t1ok) {
        for (int i = tid; i < SELB; i += 128)
            if (i >= m) sel[i] = 0ull;
        __syncthreads();
        bitonic_desc(sel, SELB, tid, 128);
        for (int i = tid; i < m; i += 128) {
            unsigned nn = 0xFFFFFFFFu - (unsigned)(sel[i] & 0xFFFFFFFFull);
            candBox[i] = g_boxes[bBase + nn];
        }
        __syncthreads();
        if (wid == 0) {
            int kept = nms_scan(sel, m, candBox, m, bBase, lane, keptBox, keptS, keptNi);
            if (lane == 0) {
                s_kept = kept;
                s_t2 = (kept < KPC && m < cnt);   // need sub-TH2 candidates
            }
        }
    } else {
        if (tid == 0) s_t2 = 1;                   // selection overflow -> full sort
    }
    __syncthreads();

    // ---- tier 2: full bitonic over entire shortlist (rare) ----
    if (s_t2) {
        int P = 1; while (P < cnt) P <<= 1;
        if (P < 2) P = 2;
        for (int i = tid; i < P; i += 128)
            if (i >= cnt) keys[i] = 0ull;
        __syncthreads();
        bitonic_desc(keys, P, tid, 128);
        for (int i = tid; i < cnt && i < SELB; i += 128) {
            unsigned nn = 0xFFFFFFFFu - (unsigned)(keys[i] & 0xFFFFFFFFull);
            candBox[i] = g_boxes[bBase + nn];
        }
        __syncthreads();
        if (wid == 0) {
            int kept = nms_scan(keys, cnt, candBox, min(cnt, SELB), bBase, lane,
                                keptBox, keptS, keptNi);
            if (lane == 0) s_kept = kept;
        }
        __syncthreads();
    }

    if (tid == 0) s_t3 = (rawCnt > CAP) || (s_kept < KPC);
    __syncthreads();

    // ---- tier 3: exact repeated-argmax greedy over all scores > 0.5 ----
    if (s_t3) {
        if (tid == 0) s_kept = 0;
        __syncthreads();
        for (int iter = 0; iter < KPC; iter++) {
            int kept = s_kept;
            ull best = 0ull;
            for (int n = tid; n < N; n += 128) {
                if (!g_mask[bBase + n]) continue;
                float s = labels[(bBase + n) * C + c];
                if (s <= 0.5f) continue;
                ull key = ((ull)__float_as_uint(s) << 32) |
                          (0xFFFFFFFFu - (unsigned)n);
                if (key <= best) continue;
                float4 bb = g_boxes[bBase + n];
                bool sup = false;
                for (int t = 0; t < kept && !sup; t++) {
                    if (keptNi[t] == n) sup = true;
                    else if (iouf(keptBox[t], bb) > 0.5f) sup = true;
                }
                if (!sup) best = key;
            }
            for (int off = 16; off; off >>= 1) {
                ull o = __shfl_xor_sync(0xffffffffu, best, off);
                if (o > best) best = o;
            }
            if (lane == 0) s_wmax[wid] = best;
            __syncthreads();
            if (wid == 0) {
                ull v = (lane < 4) ? s_wmax[lane] : 0ull;
                for (int off = 2; off; off >>= 1) {
                    ull o = __shfl_xor_sync(0xffffffffu, v, off);
                    if (o > v) v = o;
                }
                if (lane == 0) s_best = v;
            }
            __syncthreads();
            if (s_best == 0ull) break;
            if (tid == 0) {
                ull kk = s_best;
                unsigned nn = 0xFFFFFFFFu - (unsigned)(kk & 0xFFFFFFFFull);
                keptBox[s_kept] = g_boxes[bBase + nn];
                keptS[s_kept] = __uint_as_float((unsigned)(kk >> 32));
                keptNi[s_kept] = (int)nn;
                s_kept = s_kept + 1;
            }
            __syncthreads();
        }
        __syncthreads();
    }

    int kept = s_kept;
    for (int k = tid; k < KPC; k += 128) {
        g_keptScore[(size_t)col * KPC + k] = (k < kept) ? keptS[k] : 0.f;
        g_keptN   [(size_t)col * KPC + k] = (k < kept) ? keptNi[k] : 0;
    }
}

// ---------------- Phase C: histogram top-200 selection + small sort ----------------
__global__ __launch_bounds__(256) void phaseC(
    float* __restrict__ out, int B, int N, int C)
{
    int b = blockIdx.x;
    int M = C * KPC;                       // 4050
    __shared__ ull sk[4096];
    __shared__ ull sel[SELC];
    __shared__ int hist[NBIN];
    __shared__ int s_cnt, s_thr, s_fb;
    int tid = threadIdx.x;

    // reset shortlist counters for the next replay
    for (int i = tid; i < C; i += 256) g_candCnt[b * C + i] = 0;

    for (int i = tid; i < 4096; i += 256) {
        ull k = 0ull;
        if (i < M) {
            float s = g_keptScore[(size_t)b * M + i];
            k = ((ull)__float_as_uint(s) << 32) | (0xFFFFFFFFu - (unsigned)i);
        }
        sk[i] = k;
    }
    for (int i = tid; i < NBIN; i += 256) hist[i] = 0;
    if (tid == 0) { s_cnt = 0; s_thr = -1; s_fb = 0; }
    __syncthreads();

    const unsigned LOu = __float_as_uint(0.9975f);
    for (int i = tid; i < M; i += 256) {
        unsigned fb = (unsigned)(sk[i] >> 32);
        int d = (int)(fb - LOu);
        int bin = (d < 0) ? 0 : min(NBIN - 1, d >> 7);
        atomicAdd(&hist[bin], 1);
    }
    __syncthreads();

    for (int off = 1; off < NBIN; off <<= 1) {
        int v0 = hist[tid]       + ((tid + off < NBIN) ? hist[tid + off] : 0);
        int i1 = tid + 256;
        int v1 = hist[i1]        + ((i1 + off < NBIN) ? hist[i1 + off] : 0);
        __syncthreads();
        hist[tid] = v0; hist[i1] = v1;
        __syncthreads();
    }
    for (int t = tid; t < NBIN; t += 256)
        if (hist[t] >= MAXTOT && (t == NBIN - 1 || hist[t + 1] < MAXTOT)) s_thr = t;
    __syncthreads();
    int thr = s_thr;
    if (thr <= 0 || hist[thr] > SELC) { if (tid == 0) s_fb = 1; }
    __syncthreads();

    if (!s_fb) {
        for (int i = tid; i < M; i += 256) {
            unsigned fb = (unsigned)(sk[i] >> 32);
            int d = (int)(fb - LOu);
            int bin = (d < 0) ? 0 : min(NBIN - 1, d >> 7);
            if (bin >= thr) {
                int p = atomicAdd(&s_cnt, 1);
                if (p < SELC) sel[p] = sk[i];
            }
        }
        __syncthreads();
        int nsel = s_cnt;
        for (int i = tid; i < SELC; i += 256)
            if (i >= nsel) sel[i] = 0ull;
        __syncthreads();
        bitonic_desc(sel, SELC, tid, 256);
    } else {
        bitonic_desc(sk, 4096, tid, 256);
    }

    const ull* src = s_fb ? sk : sel;

    float* outBoxes   = out;
    float* outScores  = out + (size_t)B * MAXTOT * 4;
    float* outClasses = outScores + (size_t)B * MAXTOT;
    float* outCount   = outClasses + (size_t)B * MAXTOT;

    int validFlag = 0;
    if (tid < MAXTOT) {
        ull kk = src[tid];
        float s = __uint_as_float((unsigned)(kk >> 32));
        unsigned flat = 0xFFFFFFFFu - (unsigned)(kk & 0xFFFFFFFFull);
        float4 bx = make_float4(0.f, 0.f, 0.f, 0.f);
        float cls = 0.f;
        if (s > 0.f) {
            int n = g_keptN[(size_t)b * M + flat];
            bx = g_boxes[(size_t)b * N + n];
            cls = (float)(flat / KPC);
            validFlag = 1;
        }
        size_t o = (size_t)b * MAXTOT + tid;
        outBoxes[o * 4 + 0] = bx.x;
        outBoxes[o * 4 + 1] = bx.y;
        outBoxes[o * 4 + 2] = bx.z;
        outBoxes[o * 4 + 3] = bx.w;
        outScores[o]  = s;
        outClasses[o] = cls;
    }
    int vc = __syncthreads_count(validFlag);
    if (tid == 0) outCount[b] = (float)vc;
}

// ---------------- launch ----------------
extern "C" void kernel_launch(void* const* d_in, const int* in_sizes, int n_in,
                              void* d_out, int out_size) {
    const float* deltas = (const float*)d_in[0];   // pred_deltas (B,N,4)
    const float* labels = (const float*)d_in[1];   // pred_labels (B,N,C)
    const float* priors = (const float*)d_in[2];   // prior_boxes (N,4)

    int N = in_sizes[2] / 4;
    int B = in_sizes[0] / (4 * N);
    int C = in_sizes[1] / (B * N);

    dim3 gA((N + TILE - 1) / TILE, B);
    phaseA<<<gA, 256>>>(labels, deltas, priors, N, C);
    phaseB<<<B * C, 128>>>(labels, B, N, C);
    phaseC<<<B, 256>>>((float*)d_out, B, N, C);
}

// round 5
// speedup vs baseline: 2.0564x; 1.3263x over previous
#include <cuda_runtime.h>
#include <cstdint>

#define MAXB 16
#define MAXN 24564
#define MAXC 81
#define CAP  1024      // per-(b,c) candidate shortlist capacity
#define KPC  50        // MAX_PER_CLASS
#define MAXTOT 200
#define THETA 0.98f    // shortlist score threshold ( > SCORE_THR=0.5 )
#define TH2   0.995f   // tier-1 selection threshold inside shortlist
#define SELB  256      // phaseB tier-1 selection capacity (pow2)
#define SELC  512      // phaseC selection capacity (pow2)
#define NBIN  512
#define TILE  32       // anchors per pipeline stage
#define NITER 4        // tiles per block

typedef unsigned long long ull;

// ---------------- static device scratch ----------------
__device__ float4 g_boxes[MAXB * MAXN];
__device__ unsigned char g_mask[MAXB * MAXN];
__device__ ull g_cand[(size_t)MAXB * MAXC * CAP];
__device__ int g_candCnt[MAXB * MAXC];
__device__ float g_keptScore[MAXB * MAXC * KPC];
__device__ int   g_keptN[MAXB * MAXC * KPC];

__device__ __forceinline__ float iouf(float4 a, float4 b) {
    float iy1 = fmaxf(a.x, b.x);
    float ix1 = fmaxf(a.y, b.y);
    float iy2 = fminf(a.z, b.z);
    float ix2 = fminf(a.w, b.w);
    float inter = fmaxf(iy2 - iy1, 0.f) * fmaxf(ix2 - ix1, 0.f);
    float a0 = (a.z - a.x) * (a.w - a.y);
    float a1 = (b.z - b.x) * (b.w - b.y);
    return inter / (a0 + a1 - inter + 1e-8f);
}

__device__ __forceinline__ void bitonic_desc(ull* a, int P, int tid, int nthreads) {
    for (int k = 2; k <= P; k <<= 1) {
        for (int j = k >> 1; j > 0; j >>= 1) {
            for (int i = tid; i < P; i += nthreads) {
                int ixj = i ^ j;
                if (ixj > i) {
                    ull x = a[i], y = a[ixj];
                    if (((i & k) != 0) ? (x > y) : (x < y)) { a[i] = y; a[ixj] = x; }
                }
            }
            __syncthreads();
        }
    }
}

__device__ __forceinline__ void cp_async16(uint32_t saddr, const void* gaddr) {
    asm volatile("cp.async.cg.shared.global [%0], [%1], 16;" :: "r"(saddr), "l"(gaddr));
}
__device__ __forceinline__ void cp_commit() {
    asm volatile("cp.async.commit_group;");
}
template <int W> __device__ __forceinline__ void cp_wait() {
    asm volatile("cp.async.wait_group %0;" :: "n"(W));
}

// ---------------- Phase A v4: double-buffered cp.async pipeline ----------------
__global__ __launch_bounds__(256, 6) void phaseA(
    const float* __restrict__ labels,   // (B,N,C)
    const float* __restrict__ deltas,   // (B,N,4)
    const float* __restrict__ priors,   // (N,4)
    int N, int C)
{
    __shared__ __align__(16) float sL[2][TILE * MAXC];

    int tid = threadIdx.x;
    int b = blockIdx.y;
    int blk0 = blockIdx.x * (TILE * NITER);
    int nAll = min(TILE * NITER, N - blk0);
    if (nAll <= 0) return;
    int nt = (nAll + TILE - 1) / TILE;
    size_t bBase = (size_t)b * N;

    // --- decode all anchors of this block (independent of labels) ---
    if (tid < nAll) {
        int n = blk0 + tid;
        float4 pr = ((const float4*)priors)[n];
        float4 dd = ((const float4*)deltas)[bBase + n];
        float ph = pr.z - pr.x, pw = pr.w - pr.y;
        float pcy = pr.x + 0.5f * ph, pcx = pr.y + 0.5f * pw;
        float d0 = dd.x * 0.1f, d1 = dd.y * 0.1f;
        float d2 = dd.z * 0.2f, d3 = dd.w * 0.2f;
        float cy = d0 * ph + pcy, cx = d1 * pw + pcx;
        float h = expf(d2) * ph, w = expf(d3) * pw;
        float4 bx;
        bx.x = fminf(fmaxf(cy - h * 0.5f, 0.f), 1.f);
        bx.y = fminf(fmaxf(cx - w * 0.5f, 0.f), 1.f);
        bx.z = fminf(fmaxf(cy + h * 0.5f, 0.f), 1.f);
        bx.w = fminf(fmaxf(cx + w * 0.5f, 0.f), 1.f);
        g_boxes[bBase + n] = bx;
    }

    // --- prefetch helper (lambda-style macro via local func not allowed; inline) ---
    // tile t covers anchors [blk0 + t*TILE, +naT)
    const float* gtile0 = labels + (bBase + blk0) * (size_t)C;
    bool aligned = ((((uintptr_t)gtile0) & 15) == 0) && ((((size_t)TILE * C * 4) & 15) == 0);

    // prefetch tile 0
    {
        int naT = min(TILE, nAll);
        int totF = naT * C;
        const float* g = gtile0;
        if (aligned) {
            uint32_t s = (uint32_t)__cvta_generic_to_shared(sL[0]);
            int tot4 = totF >> 2;
            for (int i = tid; i < tot4; i += 256)
                cp_async16(s + i * 16, (const float4*)g + i);
            for (int i = (tot4 << 2) + tid; i < totF; i += 256) sL[0][i] = g[i];
        } else {
            for (int i = tid; i < totF; i += 256) sL[0][i] = g[i];
        }
        cp_commit();
    }

    int g8 = tid >> 3;   // anchor-in-tile for compute
    int m  = tid & 7;

    for (int t = 0; t < nt; t++) {
        // prefetch tile t+1
        if (t + 1 < nt) {
            int naT = min(TILE, nAll - (t + 1) * TILE);
            int totF = naT * C;
            const float* g = gtile0 + (size_t)(t + 1) * TILE * C;
            float* sb = sL[(t + 1) & 1];
            if (aligned) {
                uint32_t s = (uint32_t)__cvta_generic_to_shared(sb);
                int tot4 = totF >> 2;
                for (int i = tid; i < tot4; i += 256)
                    cp_async16(s + i * 16, (const float4*)g + i);
                for (int i = (tot4 << 2) + tid; i < totF; i += 256) sb[i] = g[i];
            } else {
                for (int i = tid; i < totF; i += 256) sb[i] = g[i];
            }
            cp_commit();
            cp_wait<1>();
        } else {
            cp_wait<0>();
        }
        __syncthreads();

        // --- compute tile t: 8 threads per anchor argmax + shortlist push ---
        const float* buf = sL[t & 1];
        int naT = min(TILE, nAll - t * TILE);
        int n0 = blk0 + t * TILE;

        float bv = -1e30f; int bi = 0x7fffffff;
        unsigned cb = 0;
        if (g8 < naT) {
            const float* row = buf + g8 * C;
            int k = 0;
            for (int c = m; c < C; c += 8, k++) {
                float v = row[c];
                if (v > bv) { bv = v; bi = c; }
                if (v > THETA) cb |= (1u << k);
            }
        }
        for (int off = 4; off; off >>= 1) {
            float ov = __shfl_xor_sync(0xffffffffu, bv, off);
            int   oi = __shfl_xor_sync(0xffffffffu, bi, off);
            if (ov > bv || (ov == bv && oi < bi)) { bv = ov; bi = oi; }
        }
        int mask = (bi != 0);

        if (g8 < naT) {
            if (m == 0) g_mask[bBase + n0 + g8] = (unsigned char)mask;
            if (mask && cb) {
                unsigned tail = 0xFFFFFFFFu - (unsigned)(n0 + g8);
                const float* row = buf + g8 * C;
                while (cb) {
                    int k = __ffs(cb) - 1; cb &= cb - 1;
                    int c = m + (k << 3);
                    float v = row[c];
                    int col = b * C + c;
                    int p = atomicAdd(&g_candCnt[col], 1);
                    if (p < CAP)
                        g_cand[(size_t)col * CAP + p] =
                            ((ull)__float_as_uint(v) << 32) | (ull)tail;
                }
            }
        }
        __syncthreads();   // buf[t&1] fully consumed before t+2 overwrites it
    }
}

// warp-0 sequential greedy scan over a descending-sorted array. Returns kept.
__device__ __forceinline__ int nms_scan(
    const ull* arr, int n, const float4* candBox, int prefN,
    size_t bBase, int lane,
    float4* keptBox, float* keptS, int* keptNi)
{
    int kept = 0;
    for (int i = 0; i < n && kept < KPC; i++) {
        ull kk = arr[i];
        unsigned nn = 0xFFFFFFFFu - (unsigned)(kk & 0xFFFFFFFFull);
        float4 bb = (i < prefN) ? candBox[i] : g_boxes[bBase + nn];
        bool sup = false;
        for (int t = lane; t < kept; t += 32)
            if (iouf(keptBox[t], bb) > 0.5f) sup = true;
        if (__any_sync(0xffffffffu, sup)) continue;
        if (lane == 0) {
            keptBox[kept] = bb;
            keptS[kept] = __uint_as_float((unsigned)(kk >> 32));
            keptNi[kept] = (int)nn;
        }
        kept++;
        __syncwarp();
    }
    return kept;
}

// ---------------- Phase B: per-(b,c) tiered sorted-scan greedy NMS ----------------
__global__ __launch_bounds__(128) void phaseB(
    const float* __restrict__ labels, int B, int N, int C)
{
    int col = blockIdx.x;                 // b*C + c
    int b = col / C, c = col - b * C;
    int tid = threadIdx.x, lane = tid & 31, wid = tid >> 5;

    __shared__ ull keys[CAP];
    __shared__ ull sel[SELB];
    __shared__ float4 candBox[SELB];
    __shared__ float4 keptBox[KPC];
    __shared__ float keptS[KPC];
    __shared__ int keptNi[KPC];
    __shared__ int s_selCnt, s_kept, s_t2, s_t3;
    __shared__ ull s_wmax[4];
    __shared__ ull s_best;

    int rawCnt = g_candCnt[col];
    int cnt = min(rawCnt, CAP);
    size_t bBase = (size_t)b * N;

    for (int i = tid; i < cnt; i += 128)
        keys[i] = g_cand[(size_t)col * CAP + i];
    if (tid == 0) { s_selCnt = 0; s_t2 = 0; s_t3 = 0; }
    __syncthreads();

    // ---- tier 1: select keys with score >= TH2, sort 256, scan ----
    const ull T2 = ((ull)__float_as_uint(TH2)) << 32;
    for (int i = tid; i < cnt; i += 128) {
        ull k = keys[i];
        if (k >= T2) {
            int p = atomicAdd(&s_selCnt, 1);
            if (p < SELB) sel[p] = k;
        }
    }
    __syncthreads();
    int selCnt = s_selCnt;
    bool t1ok = (selCnt <= SELB);
    int m = min(selCnt, SELB);

    if (t1ok) {
        for (int i = tid; i < SELB; i += 128)
            if (i >= m) sel[i] = 0ull;
        __syncthreads();
        bitonic_desc(sel, SELB, tid, 128);
        for (int i = tid; i < m; i += 128) {
            unsigned nn = 0xFFFFFFFFu - (unsigned)(sel[i] & 0xFFFFFFFFull);
            candBox[i] = g_boxes[bBase + nn];
        }
        __syncthreads();
        if (wid == 0) {
            int kept = nms_scan(sel, m, candBox, m, bBase, lane, keptBox, keptS, keptNi);
            if (lane == 0) {
                s_kept = kept;
                s_t2 = (kept < KPC && m < cnt);   // need sub-TH2 candidates
            }
        }
    } else {
        if (tid == 0) s_t2 = 1;                   // selection overflow -> full sort
    }
    __syncthreads();

    // ---- tier 2: full bitonic over entire shortlist (rare) ----
    if (s_t2) {
        int P = 1; while (P < cnt) P <<= 1;
        if (P < 2) P = 2;
        for (int i = tid; i < P; i += 128)
            if (i >= cnt) keys[i] = 0ull;
        __syncthreads();
        bitonic_desc(keys, P, tid, 128);
        for (int i = tid; i < cnt && i < SELB; i += 128) {
            unsigned nn = 0xFFFFFFFFu - (unsigned)(keys[i] & 0xFFFFFFFFull);
            candBox[i] = g_boxes[bBase + nn];
        }
        __syncthreads();
        if (wid == 0) {
            int kept = nms_scan(keys, cnt, candBox, min(cnt, SELB), bBase, lane,
                                keptBox, keptS, keptNi);
            if (lane == 0) s_kept = kept;
        }
        __syncthreads();
    }

    if (tid == 0) s_t3 = (rawCnt > CAP) || (s_kept < KPC);
    __syncthreads();

    // ---- tier 3: exact repeated-argmax greedy over all scores > 0.5 ----
    if (s_t3) {
        if (tid == 0) s_kept = 0;
        __syncthreads();
        for (int iter = 0; iter < KPC; iter++) {
            int kept = s_kept;
            ull best = 0ull;
            for (int n = tid; n < N; n += 128) {
                if (!g_mask[bBase + n]) continue;
                float s = labels[(bBase + n) * C + c];
                if (s <= 0.5f) continue;
                ull key = ((ull)__float_as_uint(s) << 32) |
                          (0xFFFFFFFFu - (unsigned)n);
                if (key <= best) continue;
                float4 bb = g_boxes[bBase + n];
                bool sup = false;
                for (int t = 0; t < kept && !sup; t++) {
                    if (keptNi[t] == n) sup = true;
                    else if (iouf(keptBox[t], bb) > 0.5f) sup = true;
                }
                if (!sup) best = key;
            }
            for (int off = 16; off; off >>= 1) {
                ull o = __shfl_xor_sync(0xffffffffu, best, off);
                if (o > best) best = o;
            }
            if (lane == 0) s_wmax[wid] = best;
            __syncthreads();
            if (wid == 0) {
                ull v = (lane < 4) ? s_wmax[lane] : 0ull;
                for (int off = 2; off; off >>= 1) {
                    ull o = __shfl_xor_sync(0xffffffffu, v, off);
                    if (o > v) v = o;
                }
                if (lane == 0) s_best = v;
            }
            __syncthreads();
            if (s_best == 0ull) break;
            if (tid == 0) {
                ull kk = s_best;
                unsigned nn = 0xFFFFFFFFu - (unsigned)(kk & 0xFFFFFFFFull);
                keptBox[s_kept] = g_boxes[bBase + nn];
                keptS[s_kept] = __uint_as_float((unsigned)(kk >> 32));
                keptNi[s_kept] = (int)nn;
                s_kept = s_kept + 1;
            }
            __syncthreads();
        }
        __syncthreads();
    }

    int kept = s_kept;
    for (int k = tid; k < KPC; k += 128) {
        g_keptScore[(size_t)col * KPC + k] = (k < kept) ? keptS[k] : 0.f;
        g_keptN   [(size_t)col * KPC + k] = (k < kept) ? keptNi[k] : 0;
    }
}

// ---------------- Phase C: histogram top-200 selection + small sort ----------------
__global__ __launch_bounds__(256) void phaseC(
    float* __restrict__ out, int B, int N, int C)
{
    int b = blockIdx.x;
    int M = C * KPC;                       // 4050
    __shared__ ull sk[4096];
    __shared__ ull sel[SELC];
    __shared__ int hist[NBIN];
    __shared__ int s_cnt, s_thr, s_fb;
    int tid = threadIdx.x;

    // reset shortlist counters for the next replay
    for (int i = tid; i < C; i += 256) g_candCnt[b * C + i] = 0;

    for (int i = tid; i < 4096; i += 256) {
        ull k = 0ull;
        if (i < M) {
            float s = g_keptScore[(size_t)b * M + i];
            k = ((ull)__float_as_uint(s) << 32) | (0xFFFFFFFFu - (unsigned)i);
        }
        sk[i] = k;
    }
    for (int i = tid; i < NBIN; i += 256) hist[i] = 0;
    if (tid == 0) { s_cnt = 0; s_thr = -1; s_fb = 0; }
    __syncthreads();

    const unsigned LOu = __float_as_uint(0.9975f);
    for (int i = tid; i < M; i += 256) {
        unsigned fb = (unsigned)(sk[i] >> 32);
        int d = (int)(fb - LOu);
        int bin = (d < 0) ? 0 : min(NBIN - 1, d >> 7);
        atomicAdd(&hist[bin], 1);
    }
    __syncthreads();

    for (int off = 1; off < NBIN; off <<= 1) {
        int v0 = hist[tid]       + ((tid + off < NBIN) ? hist[tid + off] : 0);
        int i1 = tid + 256;
        int v1 = hist[i1]        + ((i1 + off < NBIN) ? hist[i1 + off] : 0);
        __syncthreads();
        hist[tid] = v0; hist[i1] = v1;
        __syncthreads();
    }
    for (int t = tid; t < NBIN; t += 256)
        if (hist[t] >= MAXTOT && (t == NBIN - 1 || hist[t + 1] < MAXTOT)) s_thr = t;
    __syncthreads();
    int thr = s_thr;
    if (thr <= 0 || hist[thr] > SELC) { if (tid == 0) s_fb = 1; }
    __syncthreads();

    if (!s_fb) {
        for (int i = tid; i < M; i += 256) {
            unsigned fb = (unsigned)(sk[i] >> 32);
            int d = (int)(fb - LOu);
            int bin = (d < 0) ? 0 : min(NBIN - 1, d >> 7);
            if (bin >= thr) {
                int p = atomicAdd(&s_cnt, 1);
                if (p < SELC) sel[p] = sk[i];
            }
        }
        __syncthreads();
        int nsel = s_cnt;
        for (int i = tid; i < SELC; i += 256)
            if (i >= nsel) sel[i] = 0ull;
        __syncthreads();
        bitonic_desc(sel, SELC, tid, 256);
    } else {
        bitonic_desc(sk, 4096, tid, 256);
    }

    const ull* src = s_fb ? sk : sel;

    float* outBoxes   = out;
    float* outScores  = out + (size_t)B * MAXTOT * 4;
    float* outClasses = outScores + (size_t)B * MAXTOT;
    float* outCount   = outClasses + (size_t)B * MAXTOT;

    int validFlag = 0;
    if (tid < MAXTOT) {
        ull kk = src[tid];
        float s = __uint_as_float((unsigned)(kk >> 32));
        unsigned flat = 0xFFFFFFFFu - (unsigned)(kk & 0xFFFFFFFFull);
        float4 bx = make_float4(0.f, 0.f, 0.f, 0.f);
        float cls = 0.f;
        if (s > 0.f) {
            int n = g_keptN[(size_t)b * M + flat];
            bx = g_boxes[(size_t)b * N + n];
            cls = (float)(flat / KPC);
            validFlag = 1;
        }
        size_t o = (size_t)b * MAXTOT + tid;
        outBoxes[o * 4 + 0] = bx.x;
        outBoxes[o * 4 + 1] = bx.y;
        outBoxes[o * 4 + 2] = bx.z;
        outBoxes[o * 4 + 3] = bx.w;
        outScores[o]  = s;
        outClasses[o] = cls;
    }
    int vc = __syncthreads_count(validFlag);
    if (tid == 0) outCount[b] = (float)vc;
}

// ---------------- launch ----------------
extern "C" void kernel_launch(void* const* d_in, const int* in_sizes, int n_in,
                              void* d_out, int out_size) {
    const float* deltas = (const float*)d_in[0];   // pred_deltas (B,N,4)
    const float* labels = (const float*)d_in[1];   // pred_labels (B,N,C)
    const float* priors = (const float*)d_in[2];   // prior_boxes (N,4)

    int N = in_sizes[2] / 4;
    int B = in_sizes[0] / (4 * N);
    int C = in_sizes[1] / (B * N);

    dim3 gA((N + TILE * NITER - 1) / (TILE * NITER), B);
    phaseA<<<gA, 256>>>(labels, deltas, priors, N, C);
    phaseB<<<B * C, 128>>>(labels, B, N, C);
    phaseC<<<B, 256>>>((float*)d_out, B, N, C);
}